// round 11
// baseline (speedup 1.0000x reference)
#include <cuda_runtime.h>
#include <cuda_fp16.h>
#include <mma.h>
#include <math.h>

using namespace nvcuda;

typedef unsigned int u32;

// Problem constants
#define T_TOK   4096      // BATCH*SEQ
#define SEQLEN  2048
#define HID     2048
#define NQH     16
#define NKVH    8
#define HD      128
#define QKVW    6144      // 4096 (q+gate) + 1024 (k) + 1024 (v)
#define KDIM    2048

// ---------------------------------------------------------------------------
// Scratch (device globals — no allocation allowed)
// ---------------------------------------------------------------------------
__device__ float  g_qkv[(size_t)T_TOK * QKVW];          // fp32 qkv+gate (GEMM out)
__device__ __half g_xh[(size_t)T_TOK * HID];            // x fp16
__device__ __half g_bt[(size_t)QKVW * KDIM];            // [Wq|Wk|Wv]^T fp16 [6144][2048]
__device__ __half g_bo[(size_t)HID * KDIM];             // Wo^T fp16 [2048][2048]
__device__ __half g_qh[(size_t)T_TOK * NQH * HD];       // q (norm+rope) fp16
__device__ __half g_kh[(size_t)T_TOK * NKVH * HD];      // k (norm+rope) fp16
__device__ __half g_vh[(size_t)T_TOK * NKVH * HD];      // v fp16
__device__ __half g_ah[(size_t)T_TOK * HID];            // attn out fp16

__device__ __forceinline__ void cpa16(void* smem_dst, const void* gmem_src) {
    unsigned s = (unsigned)__cvta_generic_to_shared(smem_dst);
    asm volatile("cp.async.cg.shared.global [%0], [%1], 16;" :: "r"(s), "l"(gmem_src));
}
#define CPA_COMMIT asm volatile("cp.async.commit_group;")
#define CPA_WAIT(n) asm volatile("cp.async.wait_group %0;" :: "n"(n))

// mma.sync m16n8k16 fp16->fp32, row.col
__device__ __forceinline__ void mma16816(float* c, const u32* a, u32 b0, u32 b1) {
    asm volatile(
        "mma.sync.aligned.m16n8k16.row.col.f32.f16.f16.f32 "
        "{%0,%1,%2,%3}, {%4,%5,%6,%7}, {%8,%9}, {%0,%1,%2,%3};"
        : "+f"(c[0]), "+f"(c[1]), "+f"(c[2]), "+f"(c[3])
        : "r"(a[0]), "r"(a[1]), "r"(a[2]), "r"(a[3]), "r"(b0), "r"(b1));
}
__device__ __forceinline__ void ldsm4(u32* r, u32 addr) {
    asm volatile("ldmatrix.sync.aligned.m8n8.x4.shared.b16 {%0,%1,%2,%3}, [%4];"
                 : "=r"(r[0]), "=r"(r[1]), "=r"(r[2]), "=r"(r[3]) : "r"(addr));
}
__device__ __forceinline__ void ldsm4t(u32* r, u32 addr) {
    asm volatile("ldmatrix.sync.aligned.m8n8.x4.trans.shared.b16 {%0,%1,%2,%3}, [%4];"
                 : "=r"(r[0]), "=r"(r[1]), "=r"(r[2]), "=r"(r[3]) : "r"(addr));
}

// ---------------------------------------------------------------------------
// Prep: x fp32 -> fp16
// ---------------------------------------------------------------------------
__global__ __launch_bounds__(256) void conv_x(
    const float* __restrict__ in, __half* __restrict__ o, int n)
{
    for (int i = blockIdx.x * blockDim.x + threadIdx.x; i < n; i += gridDim.x * blockDim.x)
        o[i] = __float2half(in[i]);
}

// Prep: transpose + fp16: W [K=2048][N] fp32 -> out [N][K=2048] half
__global__ __launch_bounds__(256) void tconv(
    const float* __restrict__ W, __half* __restrict__ o, int N)
{
    __shared__ float t[32][33];
    const int n0 = blockIdx.x * 32, k0 = blockIdx.y * 32;
    const int tx = threadIdx.x, ty = threadIdx.y;
#pragma unroll
    for (int j = 0; j < 4; j++)
        t[ty + j * 8][tx] = W[(size_t)(k0 + ty + j * 8) * N + n0 + tx];
    __syncthreads();
#pragma unroll
    for (int j = 0; j < 4; j++)
        o[(size_t)(n0 + ty + j * 8) * KDIM + k0 + tx] = __float2half(t[tx][ty + j * 8]);
}

// ---------------------------------------------------------------------------
// fp16 single-pass GEMM (unchanged from round 10 — passing at ~300 TF/s)
// ---------------------------------------------------------------------------
#define GST 20480
#define G_A 0
#define G_B 10240
#define G_TOTAL (3 * GST)
#define NKSTEP 64

__global__ __launch_bounds__(128) void gemm_h1(
    const __half* __restrict__ A, const __half* __restrict__ B,
    float* __restrict__ C, int ldc)
{
    extern __shared__ __align__(16) char gsm[];
    const int tid = threadIdx.x;
    const int w   = tid >> 5;
    const int wm  = w & 1;
    const int wn  = w >> 1;
    const int m0 = blockIdx.y * 128;
    const int n0 = blockIdx.x * 128;

    wmma::fragment<wmma::accumulator, 16, 16, 16, float> acc[4][4];
#pragma unroll
    for (int i = 0; i < 4; i++)
#pragma unroll
        for (int j = 0; j < 4; j++)
            wmma::fill_fragment(acc[i][j], 0.0f);

    auto load_stage = [&](int st, int k0) {
        char* s = gsm + st * GST;
#pragma unroll
        for (int t = 0; t < 4; t++) {
            int g = tid + t * 128;
            int r = g >> 2, q = g & 3;
            cpa16(s + G_A + (r * 40 + q * 8) * 2, A + (size_t)(m0 + r) * KDIM + k0 + q * 8);
            cpa16(s + G_B + (r * 40 + q * 8) * 2, B + (size_t)(n0 + r) * KDIM + k0 + q * 8);
        }
        CPA_COMMIT;
    };

    load_stage(0, 0);
    load_stage(1, 32);

    for (int kt = 0; kt < NKSTEP; kt++) {
        if (kt == NKSTEP - 1) { CPA_WAIT(0); } else { CPA_WAIT(1); }
        __syncthreads();
        if (kt + 2 < NKSTEP) load_stage((kt + 2) % 3, (kt + 2) * 32);

        const __half* sA = (const __half*)(gsm + (kt % 3) * GST + G_A);
        const __half* sB = (const __half*)(gsm + (kt % 3) * GST + G_B);

#pragma unroll
        for (int kk = 0; kk < 32; kk += 16) {
            wmma::fragment<wmma::matrix_a, 16, 16, 16, __half, wmma::row_major> af[4];
            wmma::fragment<wmma::matrix_b, 16, 16, 16, __half, wmma::col_major> bf[4];
#pragma unroll
            for (int i = 0; i < 4; i++)
                wmma::load_matrix_sync(af[i], sA + (wm * 64 + i * 16) * 40 + kk, 40);
#pragma unroll
            for (int j = 0; j < 4; j++)
                wmma::load_matrix_sync(bf[j], sB + (wn * 64 + j * 16) * 40 + kk, 40);
#pragma unroll
            for (int i = 0; i < 4; i++)
#pragma unroll
                for (int j = 0; j < 4; j++)
                    wmma::mma_sync(acc[i][j], af[i], bf[j], acc[i][j]);
        }
    }

#pragma unroll
    for (int i = 0; i < 4; i++)
#pragma unroll
        for (int j = 0; j < 4; j++)
            wmma::store_matrix_sync(
                C + (size_t)(m0 + wm * 64 + i * 16) * ldc + n0 + wn * 64 + j * 16,
                acc[i][j], ldc, wmma::mem_row_major);
}

// ---------------------------------------------------------------------------
// RMSNorm + partial RoPE; emits q/k/v fp16 (unchanged)
// ---------------------------------------------------------------------------
__global__ __launch_bounds__(128) void normrope_kernel(
    const float* __restrict__ qkv,
    __half* __restrict__ qh, __half* __restrict__ kh, __half* __restrict__ vh,
    const float* __restrict__ qnw, const float* __restrict__ knw,
    const int* __restrict__ positions)
{
    const int t  = blockIdx.x;
    const int hh = blockIdx.y;
    const int d  = threadIdx.x;

    if (hh >= NQH + NKVH) {
        int kvh = hh - NQH - NKVH;
        float v = qkv[(size_t)t * QKVW + 5120 + kvh * HD + d];
        vh[((size_t)t * NKVH + kvh) * HD + d] = __float2half(v);
        return;
    }

    const float* vec;
    const float* w;
    __half* outp;
    if (hh < NQH) {
        vec = qkv + (size_t)t * QKVW + hh * 256;
        w = qnw;
        outp = qh + ((size_t)t * NQH + hh) * HD;
    } else {
        int kvh = hh - NQH;
        vec = qkv + (size_t)t * QKVW + 4096 + kvh * HD;
        w = knw;
        outp = kh + ((size_t)t * NKVH + kvh) * HD;
    }

    float x = vec[d];

    __shared__ float sred[4];
    __shared__ float sv[128];
    int lane = d & 31, wrp = d >> 5;
    float ss = x * x;
#pragma unroll
    for (int o = 16; o > 0; o >>= 1) ss += __shfl_xor_sync(0xffffffffu, ss, o);
    if (lane == 0) sred[wrp] = ss;
    __syncthreads();
    float tot = sred[0] + sred[1] + sred[2] + sred[3];
    float r = rsqrtf(tot * (1.0f / 128.0f) + 1e-6f);
    float y = x * r * (1.0f + w[d]);

    sv[d] = y;
    __syncthreads();

    float out = y;
    if (d < 32) {
        int j = d & 15;
        float inv = powf(10000000.0f, -(float)j * (1.0f / 16.0f));
        float ang = (float)positions[t] * inv;
        float c = cosf(ang), s = sinf(ang);
        int base = (d < 16) ? d : (d - 16);
        float x1 = sv[base];
        float x2 = sv[base + 16];
        out = (d < 16) ? (x1 * c - x2 * s) : (x1 * s + x2 * c);
    }
    outp[d] = __float2half(out);
}

// ---------------------------------------------------------------------------
// FA2-style register-resident attention, raw mma.sync m16n8k16.
// BQ=128, BK=64, 256 threads (8 warps x 16 rows each).
// grid: (16 qtiles [reversed], 16 heads, 2 batch)
// ---------------------------------------------------------------------------
#define BQ 128
#define BK 64
#define KV_LD 136                         // half stride (128 + 8)
#define KV_BYTES (64 * KV_LD * 2)         // 17408
#define OFF_K0 0
#define OFF_K1 KV_BYTES
#define OFF_V0 (2 * KV_BYTES)
#define OFF_V1 (3 * KV_BYTES)
#define OFF_MSK (4 * KV_BYTES)
#define ATT_SMEM (OFF_MSK + 2 * 64 * 4)   // 70144

__global__ __launch_bounds__(256, 1) void attn_m(
    const __half* __restrict__ qh, const __half* __restrict__ kh,
    const __half* __restrict__ vh, const float* __restrict__ qkv,
    const int* __restrict__ amask, __half* __restrict__ ao)
{
    extern __shared__ __align__(16) char asmem[];
    __half* KsA[2] = { (__half*)(asmem + OFF_K0), (__half*)(asmem + OFF_K1) };
    __half* VsA[2] = { (__half*)(asmem + OFF_V0), (__half*)(asmem + OFF_V1) };
    float* smask = (float*)(asmem + OFF_MSK);

    const int qt = (int)gridDim.x - 1 - (int)blockIdx.x;
    const int h  = blockIdx.y;
    const int b  = blockIdx.z;
    const int kvh = h >> 1;

    const __half* Qb = qh + ((size_t)b * SEQLEN * NQH + h) * HD;   // row stride 2048
    const __half* Kb = kh + ((size_t)b * SEQLEN * NKVH + kvh) * HD; // row stride 1024
    const __half* Vb = vh + ((size_t)b * SEQLEN * NKVH + kvh) * HD;
    const float*  Gb = qkv + (size_t)b * SEQLEN * QKVW + h * 256 + 128;
    const int*    mk = amask + b * SEQLEN;

    const int tid = threadIdx.x;
    const int w   = tid >> 5;
    const int lane = tid & 31;
    const int lm  = lane & 7;       // ldmatrix row within 8
    const int sel = lane >> 3;      // ldmatrix matrix select
    const int r0  = lane >> 2;      // C/A fragment low row
    const int q2  = 2 * (lane & 3); // C/A fragment col pair base

    // ---- Stage Q through K0/V0 buffers, ldmatrix into registers ----
#pragma unroll
    for (int t = 0; t < 8; t++) {
        int g = tid + t * 256;                 // 0..2047
        int r = g >> 4, q = g & 15;
        __half* dst = (r < 64 ? KsA[0] : VsA[0]) + (r & 63) * KV_LD + q * 8;
        cpa16(dst, Qb + (size_t)(qt * BQ + r) * (NQH * HD) + q * 8);
    }
    CPA_COMMIT; CPA_WAIT(0);
    __syncthreads();

    u32 qa[8][4];
    {
        __half* qbase = (w < 4) ? KsA[0] : VsA[0];
        int row = ((w * 16) & 63) + ((sel & 1) ? 8 : 0) + lm;
#pragma unroll
        for (int t = 0; t < 8; t++) {
            u32 addr = (u32)__cvta_generic_to_shared(
                qbase + row * KV_LD + t * 16 + ((sel >> 1) ? 8 : 0));
            ldsm4(qa[t], addr);
        }
    }
    __syncthreads();   // everyone done reading Q staging

    // ---- Prefetch KV tile 0 + mask 0 ----
    auto load_kv = [&](int dst, int kt) {
#pragma unroll
        for (int t = 0; t < 4; t++) {
            int g = tid + t * 256;
            int r = g >> 4, q = g & 15;
            size_t src = (size_t)(kt * 64 + r) * (NKVH * HD) + q * 8;
            cpa16(KsA[dst] + r * KV_LD + q * 8, Kb + src);
            cpa16(VsA[dst] + r * KV_LD + q * 8, Vb + src);
        }
        CPA_COMMIT;
    };
    load_kv(0, 0);
    if (tid < 64) smask[tid] = mk[tid] ? 0.0f : -1e30f;

    float m0 = -1e30f, m1 = -1e30f, l0 = 0.0f, l1 = 0.0f;
    float oacc[16][4];
#pragma unroll
    for (int i = 0; i < 16; i++)
#pragma unroll
        for (int e = 0; e < 4; e++) oacc[i][e] = 0.0f;

    const int qrow0 = qt * BQ + w * 16 + r0;
    const int qrow1 = qrow0 + 8;
    const float scale = 0.08838834764831845f;
    const int ktmax = 2 * qt + 1;

    for (int kt = 0; kt <= ktmax; kt++) {
        CPA_WAIT(0);
        __syncthreads();
        const int buf = kt & 1;
        if (kt < ktmax) {
            load_kv(buf ^ 1, kt + 1);
            if (tid < 64)
                smask[(buf ^ 1) * 64 + tid] = mk[(kt + 1) * 64 + tid] ? 0.0f : -1e30f;
        }

        const __half* Kt = KsA[buf];
        const __half* Vt = VsA[buf];

        // ---- S = Q K^T : sacc[8][4], tiles of 8 cols ----
        float sacc[8][4];
#pragma unroll
        for (int j = 0; j < 8; j++)
#pragma unroll
            for (int e = 0; e < 4; e++) sacc[j][e] = 0.0f;

#pragma unroll
        for (int t = 0; t < 8; t++) {
#pragma unroll
            for (int jp = 0; jp < 4; jp++) {
                u32 kb[4];
                int nrow = jp * 16 + ((sel >> 1) ? 8 : 0) + lm;
                int kcol = t * 16 + ((sel & 1) ? 8 : 0);
                u32 addr = (u32)__cvta_generic_to_shared(Kt + nrow * KV_LD + kcol);
                ldsm4(kb, addr);
                mma16816(sacc[2 * jp],     qa[t], kb[0], kb[1]);
                mma16816(sacc[2 * jp + 1], qa[t], kb[2], kb[3]);
            }
        }

        // ---- softmax in registers ----
        float mloc0 = -1e30f, mloc1 = -1e30f;
#pragma unroll
        for (int j = 0; j < 8; j++) {
#pragma unroll
            for (int e = 0; e < 4; e++) {
                int col = j * 8 + q2 + (e & 1);
                int sk = kt * 64 + col;
                float v = sacc[j][e] * scale + smask[buf * 64 + col];
                int sq = (e < 2) ? qrow0 : qrow1;
                if (sk > sq) v = -1e30f;
                sacc[j][e] = v;
                if (e < 2) mloc0 = fmaxf(mloc0, v);
                else       mloc1 = fmaxf(mloc1, v);
            }
        }
        mloc0 = fmaxf(mloc0, __shfl_xor_sync(0xffffffffu, mloc0, 1));
        mloc0 = fmaxf(mloc0, __shfl_xor_sync(0xffffffffu, mloc0, 2));
        mloc1 = fmaxf(mloc1, __shfl_xor_sync(0xffffffffu, mloc1, 1));
        mloc1 = fmaxf(mloc1, __shfl_xor_sync(0xffffffffu, mloc1, 2));

        float mn0 = fmaxf(m0, mloc0), mn1 = fmaxf(m1, mloc1);
        float a0 = __expf(m0 - mn0), a1 = __expf(m1 - mn1);
        m0 = mn0; m1 = mn1;

        float ls0 = 0.0f, ls1 = 0.0f;
        u32 ph0[8], ph1[8];
#pragma unroll
        for (int j = 0; j < 8; j++) {
            float e0 = __expf(sacc[j][0] - m0);
            float e1 = __expf(sacc[j][1] - m0);
            float e2 = __expf(sacc[j][2] - m1);
            float e3 = __expf(sacc[j][3] - m1);
            ls0 += e0 + e1; ls1 += e2 + e3;
            __half2 p0 = __floats2half2_rn(e0, e1);
            __half2 p1 = __floats2half2_rn(e2, e3);
            ph0[j] = *(u32*)&p0;
            ph1[j] = *(u32*)&p1;
        }
        ls0 += __shfl_xor_sync(0xffffffffu, ls0, 1);
        ls0 += __shfl_xor_sync(0xffffffffu, ls0, 2);
        ls1 += __shfl_xor_sync(0xffffffffu, ls1, 1);
        ls1 += __shfl_xor_sync(0xffffffffu, ls1, 2);
        l0 = l0 * a0 + ls0;
        l1 = l1 * a1 + ls1;

#pragma unroll
        for (int i = 0; i < 16; i++) {
            oacc[i][0] *= a0; oacc[i][1] *= a0;
            oacc[i][2] *= a1; oacc[i][3] *= a1;
        }

        // ---- O += P V ----
#pragma unroll
        for (int t = 0; t < 4; t++) {
            u32 pa[4] = { ph0[2 * t], ph1[2 * t], ph0[2 * t + 1], ph1[2 * t + 1] };
#pragma unroll
            for (int ip = 0; ip < 8; ip++) {
                u32 vb[4];
                int krow = t * 16 + ((sel & 1) ? 8 : 0) + lm;
                int ncol = ip * 16 + ((sel >> 1) ? 8 : 0);
                u32 addr = (u32)__cvta_generic_to_shared(Vt + krow * KV_LD + ncol);
                ldsm4t(vb, addr);
                mma16816(oacc[2 * ip],     pa, vb[0], vb[1]);
                mma16816(oacc[2 * ip + 1], pa, vb[2], vb[3]);
            }
        }
    }

    // ---- Epilogue: normalize, sigmoid gate, write fp16 ----
    float inv0 = 1.0f / l0, inv1 = 1.0f / l1;
    int s0 = qrow0, s1 = qrow1;
#pragma unroll
    for (int i = 0; i < 16; i++) {
        int d = i * 8 + q2;
        float2 g0 = *(const float2*)(Gb + (size_t)s0 * QKVW + d);
        float2 g1 = *(const float2*)(Gb + (size_t)s1 * QKVW + d);
        float o00 = oacc[i][0] * inv0 * (1.0f / (1.0f + __expf(-g0.x)));
        float o01 = oacc[i][1] * inv0 * (1.0f / (1.0f + __expf(-g0.y)));
        float o10 = oacc[i][2] * inv1 * (1.0f / (1.0f + __expf(-g1.x)));
        float o11 = oacc[i][3] * inv1 * (1.0f / (1.0f + __expf(-g1.y)));
        __half2 h0 = __floats2half2_rn(o00, o01);
        __half2 h1 = __floats2half2_rn(o10, o11);
        *(__half2*)(ao + ((size_t)b * SEQLEN + s0) * HID + h * HD + d) = h0;
        *(__half2*)(ao + ((size_t)b * SEQLEN + s1) * HID + h * HD + d) = h1;
    }
}

// ---------------------------------------------------------------------------
extern "C" void kernel_launch(void* const* d_in, const int* in_sizes, int n_in,
                              void* d_out, int out_size)
{
    const float* x     = (const float*)d_in[0];
    const int*   amask = (const int*)  d_in[1];
    const int*   pos   = (const int*)  d_in[2];
    const float* Wq    = (const float*)d_in[3];
    const float* Wk    = (const float*)d_in[4];
    const float* Wv    = (const float*)d_in[5];
    const float* Wo    = (const float*)d_in[6];
    const float* qnw   = (const float*)d_in[7];
    const float* knw   = (const float*)d_in[8];
    float* out = (float*)d_out;

    void *p_qkv, *p_xh, *p_bt, *p_bo, *p_qh, *p_kh, *p_vh, *p_ah;
    cudaGetSymbolAddress(&p_qkv, g_qkv);
    cudaGetSymbolAddress(&p_xh,  g_xh);
    cudaGetSymbolAddress(&p_bt,  g_bt);
    cudaGetSymbolAddress(&p_bo,  g_bo);
    cudaGetSymbolAddress(&p_qh,  g_qh);
    cudaGetSymbolAddress(&p_kh,  g_kh);
    cudaGetSymbolAddress(&p_vh,  g_vh);
    cudaGetSymbolAddress(&p_ah,  g_ah);
    float*  qkv = (float*)p_qkv;
    __half* xh  = (__half*)p_xh;
    __half* bt  = (__half*)p_bt;
    __half* bo  = (__half*)p_bo;
    __half* qh  = (__half*)p_qh;
    __half* kh  = (__half*)p_kh;
    __half* vh  = (__half*)p_vh;
    __half* ah  = (__half*)p_ah;

    // 0) Prep: convert x; transpose+convert weights
    conv_x<<<1184, 256>>>(x, xh, T_TOK * HID);
    tconv<<<dim3(4096 / 32, KDIM / 32), dim3(32, 8)>>>(Wq, bt, 4096);
    tconv<<<dim3(1024 / 32, KDIM / 32), dim3(32, 8)>>>(Wk, bt + (size_t)4096 * KDIM, 1024);
    tconv<<<dim3(1024 / 32, KDIM / 32), dim3(32, 8)>>>(Wv, bt + (size_t)5120 * KDIM, 1024);
    tconv<<<dim3(2048 / 32, KDIM / 32), dim3(32, 8)>>>(Wo, bo, 2048);

    // 1) QKV+gate projection -> g_qkv fp32 [4096][6144]
    cudaFuncSetAttribute(gemm_h1, cudaFuncAttributeMaxDynamicSharedMemorySize, G_TOTAL);
    gemm_h1<<<dim3(48, 32), 128, G_TOTAL>>>(xh, bt, qkv, QKVW);

    // 2) RMSNorm + RoPE -> fp16 q/k/v
    normrope_kernel<<<dim3(T_TOK, 32), 128>>>(qkv, qh, kh, vh, qnw, knw, pos);

    // 3) Register-resident fp16 flash attention + sigmoid gate
    cudaFuncSetAttribute(attn_m, cudaFuncAttributeMaxDynamicSharedMemorySize, ATT_SMEM);
    attn_m<<<dim3(SEQLEN / BQ, NQH, 2), 256, ATT_SMEM>>>(qh, kh, vh, qkv, amask, ah);

    // 4) Output projection -> d_out fp32
    gemm_h1<<<dim3(16, 32), 128, G_TOTAL>>>(ah, bo, out, HID);
}